// round 7
// baseline (speedup 1.0000x reference)
#include <cuda_runtime.h>

#define NN 50000
#define EE 800000
#define TT 8
#define FF 64
#define ROWS (NN * TT)          // 400000
#define NODE_ELEMS (TT * FF)    // 512 floats per node

// ---------------- scratch (static device globals; no allocation) ----------------
__device__ float g_dinv[NN];
__device__ int   g_cnt[NN];
__device__ int   g_fill[NN];
__device__ int   g_rowptr[NN + 1];
__device__ int   g_src[EE];
__device__ int   g_is64;        // 1 if edge_index is int64, 0 if int32
__device__ __align__(16) float g_bufA[(size_t)ROWS * FF];   // 102.4 MB
__device__ __align__(16) float g_bufB[(size_t)ROWS * FF];   // 102.4 MB

// buffer selector resolved in DEVICE code (no host symbol-address APIs)
__device__ __forceinline__ const float* sel_src(int s, const float* ext) {
    return s == 0 ? ext : (s == 1 ? (const float*)g_bufA : (const float*)g_bufB);
}
__device__ __forceinline__ float* sel_dst(int s, float* ext) {
    return s == 0 ? ext : (s == 1 ? (float*)g_bufA : (float*)g_bufB);
}

// edge accessor: idx in [0, 2*EE)
__device__ __forceinline__ int edge_at(const void* ei, int is64, int idx) {
    return is64 ? (int)((const long long*)ei)[idx] : ((const int*)ei)[idx];
}

// ---------------- graph preprocessing ----------------
// Detect edge_index dtype: int32 pairs (a,b) read as int64 give a+(b<<32),
// which is >= NN unless b==0. If the first 8 int64 reads are all in [0,NN),
// int64 interpretation is safe (and matches int32-with-zero-high-words too).
__global__ void k_detect(const void* ei) {
    const long long* p = (const long long*)ei;
    int ok = 1;
    for (int i = 0; i < 8; i++) {
        long long v = p[i];
        if (v < 0 || v >= NN) ok = 0;
    }
    g_is64 = ok;
}

__global__ void k_init() {
    int i = blockIdx.x * blockDim.x + threadIdx.x;
    if (i < NN) { g_cnt[i] = 0; g_fill[i] = 0; }
}

__global__ void k_count(const void* __restrict__ ei) {
    int e = blockIdx.x * blockDim.x + threadIdx.x;
    if (e < EE) {
        int is64 = g_is64;
        int c = edge_at(ei, is64, EE + e);          // target
        if (c >= 0 && c < NN) atomicAdd(&g_cnt[c], 1);
    }
}

__global__ void k_dinv() {
    int i = blockIdx.x * blockDim.x + threadIdx.x;
    if (i < NN) g_dinv[i] = rsqrtf((float)(g_cnt[i] + 1));  // +1 self loop
}

// single-block exclusive scan of g_cnt -> g_rowptr (50k elems)
__global__ void k_scan() {
    __shared__ int ps[1024];
    const int CH = 49;                      // 1024*49 = 50176 >= NN
    int tid = threadIdx.x;
    int start = tid * CH;
    int end = min(start + CH, NN);
    int s = 0;
    for (int i = start; i < end; i++) s += g_cnt[i];
    ps[tid] = s;
    __syncthreads();
    for (int off = 1; off < 1024; off <<= 1) {
        int v = (tid >= off) ? ps[tid - off] : 0;
        __syncthreads();
        ps[tid] += v;
        __syncthreads();
    }
    int run = (tid == 0) ? 0 : ps[tid - 1];
    for (int i = start; i < end; i++) { g_rowptr[i] = run; run += g_cnt[i]; }
    if (tid == 1023) g_rowptr[NN] = run;    // == EE (if all targets in range)
}

__global__ void k_scatter(const void* __restrict__ ei) {
    int e = blockIdx.x * blockDim.x + threadIdx.x;
    if (e < EE) {
        int is64 = g_is64;
        int r = edge_at(ei, is64, e);               // source
        int c = edge_at(ei, is64, EE + e);          // target
        if (c >= 0 && c < NN && r >= 0 && r < NN) {
            int p = g_rowptr[c] + atomicAdd(&g_fill[c], 1);
            g_src[p] = r;
        }
    }
}

// ---------------- GEMM: out[row] = dinv[row/T] * (in[row] @ W), row-major 64x64 W ----
// block: 256 threads, tile: 64 rows. Thread (rl = tid>>2, cg = (tid&3)*4) computes
// 16 outputs at cols {cg + 16*j + u}.
__global__ void __launch_bounds__(256) k_gemm(const float* __restrict__ in_ext,
                                              const float* __restrict__ W,
                                              float* __restrict__ out_ext,
                                              int in_sel, int out_sel) {
    const float* in = sel_src(in_sel, in_ext);
    float* out = sel_dst(out_sel, out_ext);

    __shared__ __align__(16) float ws[64 * 64];
    __shared__ __align__(16) float xs[64 * 68];   // pad 68 to kill bank conflicts
    int tid = threadIdx.x;
    for (int i = tid; i < 4096; i += 256) ws[i] = W[i];

    int rl = tid >> 2;
    int cg = (tid & 3) * 4;
    const int ntiles = ROWS / 64;                 // 6250 exact

    for (int tile = blockIdx.x; tile < ntiles; tile += gridDim.x) {
        size_t row0 = (size_t)tile * 64;
        __syncthreads();                          // protect xs reuse (and ws 1st iter)
        const float4* gsrc = (const float4*)(in + row0 * 64);
        for (int i = tid; i < 1024; i += 256) {
            float4 v = gsrc[i];
            *(float4*)&xs[(i >> 4) * 68 + (i & 15) * 4] = v;
        }
        __syncthreads();

        float4 acc[4];
        #pragma unroll
        for (int j = 0; j < 4; j++) acc[j] = make_float4(0.f, 0.f, 0.f, 0.f);

        const float* xr = &xs[rl * 68];
        #pragma unroll 8
        for (int k = 0; k < 64; k++) {
            float a = xr[k];
            #pragma unroll
            for (int j = 0; j < 4; j++) {
                float4 w = *(const float4*)&ws[k * 64 + cg + j * 16];
                acc[j].x = fmaf(a, w.x, acc[j].x);
                acc[j].y = fmaf(a, w.y, acc[j].y);
                acc[j].z = fmaf(a, w.z, acc[j].z);
                acc[j].w = fmaf(a, w.w, acc[j].w);
            }
        }

        int grow = (int)row0 + rl;
        float sc = g_dinv[grow >> 3];             // node = row / T
        float* orow = out + (size_t)grow * 64;
        #pragma unroll
        for (int j = 0; j < 4; j++) {
            float4 o = make_float4(acc[j].x * sc, acc[j].y * sc,
                                   acc[j].z * sc, acc[j].w * sc);
            *(float4*)&orow[cg + j * 16] = o;
        }
    }
}

// ---------------- aggregation: warp per target node ----------------
// out[c] = relu(dinv[c] * (hs[c] + sum_{r in Nin(c)} hs[r]) + b)
__device__ __forceinline__ float4 f4add(float4 a, float4 b) {
    return make_float4(a.x + b.x, a.y + b.y, a.z + b.z, a.w + b.w);
}

__global__ void __launch_bounds__(256) k_agg(const float* __restrict__ hs_ext,
                                             const float* __restrict__ bias,
                                             float* __restrict__ out_ext,
                                             int in_sel, int out_sel) {
    const float* hs = sel_src(in_sel, hs_ext);
    float* outp = sel_dst(out_sel, out_ext);

    int gw = (blockIdx.x * 256 + threadIdx.x) >> 5;
    int lane = threadIdx.x & 31;
    if (gw >= NN) return;
    int c = gw;
    int beg = g_rowptr[c];
    int end = g_rowptr[c + 1];

    size_t sb = (size_t)c * NODE_ELEMS + lane * 4;
    float4 a0 = *(const float4*)(hs + sb);           // self-loop term
    float4 a1 = *(const float4*)(hs + sb + 128);
    float4 a2 = *(const float4*)(hs + sb + 256);
    float4 a3 = *(const float4*)(hs + sb + 384);

    for (int base = beg; base < end; base += 32) {
        int nn = min(32, end - base);
        int s = (base + lane < end) ? g_src[base + lane] : 0;
        for (int t = 0; t < nn; t++) {
            int si = __shfl_sync(0xffffffffu, s, t);
            const float* p = hs + (size_t)si * NODE_ELEMS + lane * 4;
            a0 = f4add(a0, *(const float4*)p);
            a1 = f4add(a1, *(const float4*)(p + 128));
            a2 = f4add(a2, *(const float4*)(p + 256));
            a3 = f4add(a3, *(const float4*)(p + 384));
        }
    }

    float dc = g_dinv[c];
    float4 bv = *(const float4*)&bias[(lane & 15) * 4];   // f = idx & 63
    float* o = outp + (size_t)c * NODE_ELEMS + lane * 4;
    #pragma unroll
    for (int j = 0; j < 4; j++) {
        float4 a = (j == 0) ? a0 : (j == 1) ? a1 : (j == 2) ? a2 : a3;
        float4 r = make_float4(fmaxf(fmaf(a.x, dc, bv.x), 0.f),
                               fmaxf(fmaf(a.y, dc, bv.y), 0.f),
                               fmaxf(fmaf(a.z, dc, bv.z), 0.f),
                               fmaxf(fmaf(a.w, dc, bv.w), 0.f));
        *(float4*)(o + j * 128) = r;
    }
}

// ---------------- launch ----------------
extern "C" void kernel_launch(void* const* d_in, const int* in_sizes, int n_in,
                              void* d_out, int out_size) {
    const float* x  = (const float*)d_in[0];       // [N, T, 64]
    const void*  ei = d_in[1];                     // [2, E] int32 OR int64 (auto-detected)
    const float* W1 = (const float*)d_in[2];
    const float* b1 = (const float*)d_in[3];
    const float* W2 = (const float*)d_in[4];
    const float* b2 = (const float*)d_in[5];
    float* out = (float*)d_out;

    // graph build
    k_detect <<<1, 1>>>(ei);
    k_init   <<<(NN + 255) / 256, 256>>>();
    k_count  <<<(EE + 255) / 256, 256>>>(ei);
    k_dinv   <<<(NN + 255) / 256, 256>>>();
    k_scan   <<<1, 1024>>>();
    k_scatter<<<(EE + 255) / 256, 256>>>(ei);

    // layer 1: bufA = dinv ⊙ (x @ W1); bufB = relu-agg(bufA)
    k_gemm<<<1250, 256>>>(x, W1, nullptr, 0, 1);
    k_agg <<<(NN * 32 + 255) / 256, 256>>>(nullptr, b1, nullptr, 1, 2);
    // layer 2: bufA = dinv ⊙ (bufB @ W2); out = relu-agg(bufA)
    k_gemm<<<1250, 256>>>(nullptr, W2, nullptr, 2, 1);
    k_agg <<<(NN * 32 + 255) / 256, 256>>>(nullptr, b2, out, 1, 0);
}